// round 1
// baseline (speedup 1.0000x reference)
#include <cuda_runtime.h>

// Problem constants
#define NB 4
#define NQ 256
#define NK 1024
#define ND 512   // DQ = DK = DV
#define NH 256

// Scratch (static device globals; no runtime allocation)
__device__ float g_qproj[NB * NQ * NH];        // [b*Q+q][h]      1 MB
__device__ float g_kT[NB * NH * NK];           // [b][h][k]       4 MB
__device__ float g_attn[NB * NQ * NK];         // [b][q][k]       4 MB

__device__ __forceinline__ float tanh_fast(float x) {
    float y;
    asm("tanh.approx.f32 %0, %1;" : "=f"(y) : "f"(x));
    return y;
}

// ---------------------------------------------------------------------------
// NT GEMM: C[M,N] = A[M,K] * W[N,K]^T   (K = 512, N = 256 fixed)
// TRANS_OUT=false -> g_qproj[m][n] ; TRANS_OUT=true -> g_kT[b][n][k]
// Tile 64x64, k-tile 32, 256 threads, 4x4 micro-tile.
// ---------------------------------------------------------------------------
template <bool TRANS_OUT>
__global__ void __launch_bounds__(256) proj_kernel(const float* __restrict__ A,
                                                   const float* __restrict__ W) {
    const int K = ND;
    __shared__ float As[64][33];
    __shared__ float Ws[64][33];

    const int tid = threadIdx.x;
    const int m0 = blockIdx.y * 64;
    const int n0 = blockIdx.x * 64;
    const int lk = tid & 31;       // k within tile
    const int lr = tid >> 5;       // row group (0..7)
    const int ty = tid >> 4;       // 0..15
    const int tx = tid & 15;       // 0..15

    float acc[4][4] = {};

    for (int k0 = 0; k0 < K; k0 += 32) {
#pragma unroll
        for (int i = 0; i < 8; i++) {
            As[lr + i * 8][lk] = A[(m0 + lr + i * 8) * K + k0 + lk];
            Ws[lr + i * 8][lk] = W[(n0 + lr + i * 8) * K + k0 + lk];
        }
        __syncthreads();
#pragma unroll
        for (int kk = 0; kk < 32; kk++) {
            float a[4], w[4];
#pragma unroll
            for (int i = 0; i < 4; i++) a[i] = As[ty * 4 + i][kk];
#pragma unroll
            for (int j = 0; j < 4; j++) w[j] = Ws[tx * 4 + j][kk];
#pragma unroll
            for (int i = 0; i < 4; i++)
#pragma unroll
                for (int j = 0; j < 4; j++) acc[i][j] += a[i] * w[j];
        }
        __syncthreads();
    }

#pragma unroll
    for (int i = 0; i < 4; i++) {
        const int gm = m0 + ty * 4 + i;
#pragma unroll
        for (int j = 0; j < 4; j++) {
            const int gn = n0 + tx * 4 + j;
            if (TRANS_OUT) {
                const int b = gm >> 10;          // key row -> (b, k)
                const int kk2 = gm & 1023;
                g_kT[(b * NH + gn) * NK + kk2] = acc[i][j];
            } else {
                g_qproj[gm * NH + gn] = acc[i][j];
            }
        }
    }
}

// ---------------------------------------------------------------------------
// Scores + masked softmax.
// One block = (batch b, 4 query rows). 256 threads; thread t owns keys
// {t, t+256, t+512, t+768}. Inner loop over h with coalesced kT loads.
// ---------------------------------------------------------------------------
__global__ void __launch_bounds__(256) scores_kernel(const int* __restrict__ valid_lens,
                                                     const float* __restrict__ wv) {
    __shared__ float qs[4][NH];    // 4 KB
    __shared__ float ss[4][NK];    // 16 KB
    __shared__ float wvs[NH];      // 1 KB
    __shared__ float red[256];     // 1 KB

    const int tid = threadIdx.x;
    const int b = blockIdx.x >> 6;          // 64 blocks per batch
    const int q0 = (blockIdx.x & 63) * 4;

    wvs[tid] = wv[tid];
#pragma unroll
    for (int r = 0; r < 4; r++)
        qs[r][tid] = g_qproj[(b * NQ + q0 + r) * NH + tid];
    __syncthreads();

    float acc[4][4] = {};   // [q row][k slice]
    const float* kp = g_kT + (size_t)b * NH * NK + tid;

#pragma unroll 4
    for (int h = 0; h < NH; h++) {
        const float kv0 = kp[h * NK];
        const float kv1 = kp[h * NK + 256];
        const float kv2 = kp[h * NK + 512];
        const float kv3 = kp[h * NK + 768];
        const float w = wvs[h];
#pragma unroll
        for (int r = 0; r < 4; r++) {
            const float qv = qs[r][h];
            acc[r][0] += w * tanh_fast(qv + kv0);
            acc[r][1] += w * tanh_fast(qv + kv1);
            acc[r][2] += w * tanh_fast(qv + kv2);
            acc[r][3] += w * tanh_fast(qv + kv3);
        }
    }

    const int vl = valid_lens[b];
#pragma unroll
    for (int r = 0; r < 4; r++)
#pragma unroll
        for (int j = 0; j < 4; j++) {
            const int k = j * 256 + tid;
            ss[r][k] = (k < vl) ? acc[r][j] : -1e6f;
        }
    __syncthreads();

    // Masked softmax per q row, then write attention weights
    for (int r = 0; r < 4; r++) {
        float lm = -1e30f;
#pragma unroll
        for (int j = 0; j < 4; j++) lm = fmaxf(lm, ss[r][j * 256 + tid]);
        red[tid] = lm;
        __syncthreads();
        for (int s = 128; s > 0; s >>= 1) {
            if (tid < s) red[tid] = fmaxf(red[tid], red[tid + s]);
            __syncthreads();
        }
        const float mx = red[0];
        __syncthreads();

        float e[4], lsum = 0.0f;
#pragma unroll
        for (int j = 0; j < 4; j++) {
            e[j] = __expf(ss[r][j * 256 + tid] - mx);
            lsum += e[j];
        }
        red[tid] = lsum;
        __syncthreads();
        for (int s = 128; s > 0; s >>= 1) {
            if (tid < s) red[tid] += red[tid + s];
            __syncthreads();
        }
        const float inv = 1.0f / red[0];
        __syncthreads();

        float* ap = g_attn + (size_t)(b * NQ + q0 + r) * NK;
#pragma unroll
        for (int j = 0; j < 4; j++) ap[j * 256 + tid] = e[j] * inv;
    }
}

// ---------------------------------------------------------------------------
// out[b][q][v] = sum_k attn[b][q][k] * values[b][k][v]   (NN GEMM per batch)
// Tile 64x64, k-tile 32, 256 threads, 4x4 micro-tile.
// ---------------------------------------------------------------------------
__global__ void __launch_bounds__(256) av_kernel(const float* __restrict__ values,
                                                 float* __restrict__ out) {
    __shared__ float As[64][33];
    __shared__ float Bs[32][64];

    const int tid = threadIdx.x;
    const int b = blockIdx.z;
    const int m0 = blockIdx.y * 64;   // q tile
    const int n0 = blockIdx.x * 64;   // v tile
    const float* A = g_attn + (size_t)b * NQ * NK;
    const float* Bv = values + (size_t)b * NK * ND;

    const int lkA = tid & 31, lrA = tid >> 5;
    const int lnB = tid & 63, lkB = tid >> 6;
    const int ty = tid >> 4, tx = tid & 15;

    float acc[4][4] = {};

    for (int k0 = 0; k0 < NK; k0 += 32) {
#pragma unroll
        for (int i = 0; i < 8; i++)
            As[lrA + i * 8][lkA] = A[(m0 + lrA + i * 8) * NK + k0 + lkA];
#pragma unroll
        for (int i = 0; i < 8; i++)
            Bs[lkB + i * 4][lnB] = Bv[(k0 + lkB + i * 4) * ND + n0 + lnB];
        __syncthreads();
#pragma unroll
        for (int kk = 0; kk < 32; kk++) {
            float a[4], w[4];
#pragma unroll
            for (int i = 0; i < 4; i++) a[i] = As[ty * 4 + i][kk];
#pragma unroll
            for (int j = 0; j < 4; j++) w[j] = Bs[kk][tx * 4 + j];
#pragma unroll
            for (int i = 0; i < 4; i++)
#pragma unroll
                for (int j = 0; j < 4; j++) acc[i][j] += a[i] * w[j];
        }
        __syncthreads();
    }

#pragma unroll
    for (int i = 0; i < 4; i++)
#pragma unroll
        for (int j = 0; j < 4; j++)
            out[(size_t)(b * NQ + m0 + ty * 4 + i) * ND + n0 + tx * 4 + j] = acc[i][j];
}

// ---------------------------------------------------------------------------
extern "C" void kernel_launch(void* const* d_in, const int* in_sizes, int n_in,
                              void* d_out, int out_size) {
    const float* queries    = (const float*)d_in[0];  // (4,256,512)
    const float* keys       = (const float*)d_in[1];  // (4,1024,512)
    const float* values     = (const float*)d_in[2];  // (4,1024,512)
    const int*   valid_lens = (const int*)d_in[3];    // (4,)
    const float* Wq         = (const float*)d_in[4];  // (256,512)
    const float* Wk         = (const float*)d_in[5];  // (256,512)
    const float* wv         = (const float*)d_in[6];  // (256,)
    float* out = (float*)d_out;                       // (4,256,512)

    (void)in_sizes; (void)n_in; (void)out_size;

    // q projection: M = B*Q = 1024
    proj_kernel<false><<<dim3(NH / 64, (NB * NQ) / 64), 256>>>(queries, Wq);
    // k projection (transposed output): M = B*K = 4096
    proj_kernel<true><<<dim3(NH / 64, (NB * NK) / 64), 256>>>(keys, Wk);
    // scores + masked softmax: 256 blocks (4 q rows each)
    scores_kernel<<<(NB * NQ) / 4, 256>>>(valid_lens, wv);
    // attn @ values
    av_kernel<<<dim3(ND / 64, NQ / 64, NB), 256>>>(values, out);
}

// round 3
// speedup vs baseline: 1.0846x; 1.0846x over previous
#include <cuda_runtime.h>
#include <cuda_fp16.h>

// Problem constants
#define NB 4
#define NQ 256
#define NK 1024
#define ND 512
#define NH 256

// GEMM tiling
#define BM 64
#define BN 64
#define BK 16
#define TM 8
#define TN 4

__device__ __align__(16) float g_qproj[NB * NQ * NH];  // [bq][h]
__device__ __align__(16) float g_kT[NB * NH * NK];     // [b][h][k]
__device__ __align__(16) float g_attn[NB * NQ * NK];   // [bq][k]

__device__ __forceinline__ __half2 h2tanh_fast(__half2 a) {
    __half2 r;
    asm("tanh.approx.f16x2 %0, %1;"
        : "=r"(*reinterpret_cast<unsigned int*>(&r))
        : "r"(*reinterpret_cast<unsigned int*>(&a)));
    return r;
}

// ---------------------------------------------------------------------------
// Shared GEMM pieces: smem k-major [BK][BM+4], vector LDS, 8x4 micro-tile.
// ---------------------------------------------------------------------------
__device__ __forceinline__ void stsT(float S[BK][BM + 4], float4 v, int lk, int row) {
    S[lk + 0][row] = v.x;
    S[lk + 1][row] = v.y;
    S[lk + 2][row] = v.z;
    S[lk + 3][row] = v.w;
}

__device__ __forceinline__ void mm_tile(const float As[BK][BM + 4],
                                        const float Bs[BK][BN + 4],
                                        float acc[TM][TN], int tx, int ty) {
#pragma unroll
    for (int kk = 0; kk < BK; kk++) {
        float4 a0 = *reinterpret_cast<const float4*>(&As[kk][ty * TM]);
        float4 a1 = *reinterpret_cast<const float4*>(&As[kk][ty * TM + 4]);
        float4 bv = *reinterpret_cast<const float4*>(&Bs[kk][tx * TN]);
        float a[8] = {a0.x, a0.y, a0.z, a0.w, a1.x, a1.y, a1.z, a1.w};
        float b[4] = {bv.x, bv.y, bv.z, bv.w};
#pragma unroll
        for (int i = 0; i < TM; i++)
#pragma unroll
            for (int j = 0; j < TN; j++)
                acc[i][j] = fmaf(a[i], b[j], acc[i][j]);
    }
}

// ---------------------------------------------------------------------------
// Fused q/k projection (NT GEMMs).
//  bid <  64 : qproj  C[bq][h]   = queries(1024x512) @ Wq(256x512)^T
//  bid >= 64 : kproj  kT[b][h][k] = Wk(256x512) @ keys(4096x512)^T  (coalesced!)
// ---------------------------------------------------------------------------
__global__ void __launch_bounds__(128) proj_gemm(const float* __restrict__ Qin,
                                                 const float* __restrict__ Kin,
                                                 const float* __restrict__ Wq,
                                                 const float* __restrict__ Wk) {
    __shared__ __align__(16) float As[BK][BM + 4];
    __shared__ __align__(16) float Bs[BK][BN + 4];
    const int K = 512;
    const int bid = blockIdx.x, tid = threadIdx.x;

    const float *A, *B;
    int m0, n0;
    const bool isq = bid < 64;
    if (isq) {
        m0 = (bid >> 2) * BM;  // 16 m-tiles over 1024 query rows
        n0 = (bid & 3) * BN;   // 4 n-tiles over 256 h
        A = Qin; B = Wq;
    } else {
        const int kb = bid - 64;
        m0 = (kb >> 6) * BM;   // 4 m-tiles over 256 h
        n0 = (kb & 63) * BN;   // 64 n-tiles over 4096 (b,k)
        A = Wk; B = Kin;
    }

    const int lr = tid >> 2;
    const int lk = (tid & 3) << 2;
    const float* Ap = A + (size_t)(m0 + lr) * K + lk;
    const float* Bp = B + (size_t)(n0 + lr) * K + lk;

    float4 a0 = *(const float4*)Ap;
    float4 a1 = *(const float4*)(Ap + 32 * K);
    float4 b0 = *(const float4*)Bp;
    float4 b1 = *(const float4*)(Bp + 32 * K);
    stsT(As, a0, lk, lr); stsT(As, a1, lk, lr + 32);
    stsT(Bs, b0, lk, lr); stsT(Bs, b1, lk, lr + 32);
    __syncthreads();

    float acc[TM][TN] = {};
    const int tx = tid & 15, ty = tid >> 4;

    for (int k0 = BK; k0 < K; k0 += BK) {
        a0 = *(const float4*)(Ap + k0);
        a1 = *(const float4*)(Ap + 32 * K + k0);
        b0 = *(const float4*)(Bp + k0);
        b1 = *(const float4*)(Bp + 32 * K + k0);
        mm_tile(As, Bs, acc, tx, ty);
        __syncthreads();
        stsT(As, a0, lk, lr); stsT(As, a1, lk, lr + 32);
        stsT(Bs, b0, lk, lr); stsT(Bs, b1, lk, lr + 32);
        __syncthreads();
    }
    mm_tile(As, Bs, acc, tx, ty);

#pragma unroll
    for (int i = 0; i < TM; i++) {
        const int gm = m0 + ty * TM + i;
        float4 v = make_float4(acc[i][0], acc[i][1], acc[i][2], acc[i][3]);
        if (isq) {
            *(float4*)&g_qproj[(size_t)gm * NH + n0 + tx * TN] = v;
        } else {
            const int gb = n0 >> 10;
            const int kx = (n0 & 1023) + tx * TN;
            *(float4*)&g_kT[(size_t)(gb * NH + gm) * NK + kx] = v;
        }
    }
}

// ---------------------------------------------------------------------------
// Scores + masked softmax. 128 blocks (single wave), 512 threads.
// Block = (batch, 8 query rows). Thread owns keys {2t, 2t+1}.
// tanh via tanh.approx.f16x2 (2 per MUFU inst), fp32 accumulation.
// ---------------------------------------------------------------------------
__global__ void __launch_bounds__(512) scores_kernel(const int* __restrict__ vlen,
                                                     const float* __restrict__ wv) {
    __shared__ float qsT[NH][8];
    __shared__ __half2 qsh[NH][4];   // (r0,r1),(r2,r3),(r4,r5),(r6,r7) per h
    __shared__ float wvs[NH];
    __shared__ float wred[16][8];
    __shared__ float bred[8];

    const int tid = threadIdx.x;
    const int b = blockIdx.x >> 5;          // 32 blocks per batch
    const int q0 = (blockIdx.x & 31) << 3;  // 8 q rows per block

    if (tid < NH) wvs[tid] = wv[tid];
#pragma unroll
    for (int i = 0; i < 4; i++) {
        const int idx = tid + i * 512;
        const int h = idx >> 3, r = idx & 7;
        qsT[h][r] = g_qproj[(size_t)(b * NQ + q0 + r) * NH + h];
    }
    __syncthreads();
#pragma unroll
    for (int i = 0; i < 2; i++) {
        const int idx = tid + i * 512;
        const int h = idx >> 2, rp = idx & 3;
        qsh[h][rp] = __floats2half2_rn(qsT[h][2 * rp], qsT[h][2 * rp + 1]);
    }
    __syncthreads();

    float acc[8][2] = {};
    const float2* kp = reinterpret_cast<const float2*>(g_kT + (size_t)b * NH * NK) + tid;

#pragma unroll 4
    for (int h = 0; h < NH; h++) {
        const float2 kv = kp[h * (NK / 2)];
        const __half2 k0 = __float2half2_rn(kv.x);
        const __half2 k1 = __float2half2_rn(kv.y);
        const float w = wvs[h];
#pragma unroll
        for (int rp = 0; rp < 4; rp++) {
            const __half2 q2 = qsh[h][rp];
            const float2 f0 = __half22float2(h2tanh_fast(__hadd2(q2, k0)));
            const float2 f1 = __half22float2(h2tanh_fast(__hadd2(q2, k1)));
            acc[2 * rp][0]     = fmaf(w, f0.x, acc[2 * rp][0]);
            acc[2 * rp + 1][0] = fmaf(w, f0.y, acc[2 * rp + 1][0]);
            acc[2 * rp][1]     = fmaf(w, f1.x, acc[2 * rp][1]);
            acc[2 * rp + 1][1] = fmaf(w, f1.y, acc[2 * rp + 1][1]);
        }
    }

    const int vl = vlen[b];
    const int kb2 = tid * 2;
    float s0[8], s1[8], rm[8];
#pragma unroll
    for (int r = 0; r < 8; r++) {
        s0[r] = (kb2 < vl) ? acc[r][0] : -1e6f;
        s1[r] = (kb2 + 1 < vl) ? acc[r][1] : -1e6f;
        rm[r] = fmaxf(s0[r], s1[r]);
    }
#pragma unroll
    for (int o = 16; o > 0; o >>= 1)
#pragma unroll
        for (int r = 0; r < 8; r++)
            rm[r] = fmaxf(rm[r], __shfl_xor_sync(0xffffffffu, rm[r], o));
    const int wid = tid >> 5, lane = tid & 31;
    if (lane == 0)
#pragma unroll
        for (int r = 0; r < 8; r++) wred[wid][r] = rm[r];
    __syncthreads();
    if (tid < 8) {
        float m = wred[0][tid];
#pragma unroll
        for (int w2 = 1; w2 < 16; w2++) m = fmaxf(m, wred[w2][tid]);
        bred[tid] = m;
    }
    __syncthreads();

    float e0[8], e1[8], rs[8];
#pragma unroll
    for (int r = 0; r < 8; r++) {
        const float mx = bred[r];
        e0[r] = __expf(s0[r] - mx);
        e1[r] = __expf(s1[r] - mx);
        rs[r] = e0[r] + e1[r];
    }
#pragma unroll
    for (int o = 16; o > 0; o >>= 1)
#pragma unroll
        for (int r = 0; r < 8; r++)
            rs[r] += __shfl_xor_sync(0xffffffffu, rs[r], o);
    if (lane == 0)
#pragma unroll
        for (int r = 0; r < 8; r++) wred[wid][r] = rs[r];
    __syncthreads();
    if (tid < 8) {
        float s = 0.0f;
#pragma unroll
        for (int w2 = 0; w2 < 16; w2++) s += wred[w2][tid];
        bred[tid] = 1.0f / s;
    }
    __syncthreads();

#pragma unroll
    for (int r = 0; r < 8; r++) {
        const float inv = bred[r];
        float2 o2 = make_float2(e0[r] * inv, e1[r] * inv);
        *reinterpret_cast<float2*>(&g_attn[(size_t)(b * NQ + q0 + r) * NK + kb2]) = o2;
    }
}

// ---------------------------------------------------------------------------
// out[b][q][v] = attn[b][q][:] @ values[b][:][v]  (NN GEMM per batch)
// ---------------------------------------------------------------------------
__global__ void __launch_bounds__(128) av_gemm(const float* __restrict__ V,
                                               float* __restrict__ out) {
    __shared__ __align__(16) float As[BK][BM + 4];
    __shared__ __align__(16) float Bs[BK][BN + 4];
    const int tid = threadIdx.x;
    const int b = blockIdx.z;
    const int m0 = blockIdx.y * BM;
    const int n0 = blockIdx.x * BN;
    const float* A = g_attn + (size_t)b * NQ * NK;
    const float* B = V + (size_t)b * NK * ND;

    const int lr = tid >> 2, lk = (tid & 3) << 2;   // A (transpose) loader
    const int bk = tid >> 4, bn = (tid & 15) << 2;  // B (direct) loader
    const float* Ap = A + (size_t)(m0 + lr) * NK + lk;
    const float* Bp = B + (size_t)bk * ND + n0 + bn;

    float4 a0 = *(const float4*)Ap;
    float4 a1 = *(const float4*)(Ap + 32 * NK);
    float4 b0 = *(const float4*)Bp;
    float4 b1 = *(const float4*)(Bp + 8 * ND);
    stsT(As, a0, lk, lr); stsT(As, a1, lk, lr + 32);
    *(float4*)&Bs[bk][bn] = b0;
    *(float4*)&Bs[bk + 8][bn] = b1;
    __syncthreads();

    float acc[TM][TN] = {};
    const int tx = tid & 15, ty = tid >> 4;

    for (int k0 = BK; k0 < NK; k0 += BK) {
        a0 = *(const float4*)(Ap + k0);
        a1 = *(const float4*)(Ap + 32 * NK + k0);
        b0 = *(const float4*)(Bp + (size_t)k0 * ND);
        b1 = *(const float4*)(Bp + (size_t)(k0 + 8) * ND);
        mm_tile(As, Bs, acc, tx, ty);
        __syncthreads();
        stsT(As, a0, lk, lr); stsT(As, a1, lk, lr + 32);
        *(float4*)&Bs[bk][bn] = b0;
        *(float4*)&Bs[bk + 8][bn] = b1;
        __syncthreads();
    }
    mm_tile(As, Bs, acc, tx, ty);

#pragma unroll
    for (int i = 0; i < TM; i++) {
        const int gm = m0 + ty * TM + i;
        float4 v = make_float4(acc[i][0], acc[i][1], acc[i][2], acc[i][3]);
        *(float4*)&out[(size_t)(b * NQ + gm) * ND + n0 + tx * TN] = v;
    }
}

// ---------------------------------------------------------------------------
extern "C" void kernel_launch(void* const* d_in, const int* in_sizes, int n_in,
                              void* d_out, int out_size) {
    const float* queries    = (const float*)d_in[0];  // (4,256,512)
    const float* keys       = (const float*)d_in[1];  // (4,1024,512)
    const float* values     = (const float*)d_in[2];  // (4,1024,512)
    const int*   valid_lens = (const int*)d_in[3];    // (4,)
    const float* Wq         = (const float*)d_in[4];  // (256,512)
    const float* Wk         = (const float*)d_in[5];  // (256,512)
    const float* wv         = (const float*)d_in[6];  // (256,)
    float* out = (float*)d_out;                       // (4,256,512)

    (void)in_sizes; (void)n_in; (void)out_size;

    // q + k projections fused: 64 qproj tiles + 256 kproj tiles
    proj_gemm<<<320, 128>>>(queries, keys, Wq, Wk);
    // scores + masked softmax: 128 blocks (one wave), 8 q rows each
    scores_kernel<<<128, 512>>>(valid_lens, wv);
    // attn @ values
    av_gemm<<<dim3(ND / BN, NQ / BM, NB), 128>>>(values, out);
}

// round 4
// speedup vs baseline: 1.3201x; 1.2171x over previous
#include <cuda_runtime.h>
#include <cuda_fp16.h>

// Problem constants
#define NB 4
#define NQ 256
#define NK 1024
#define ND 512
#define NH 256

// GEMM tiling
#define BM 64
#define BN 64
#define BK 16
#define TM 8
#define TN 4
#define KSPLIT 4
#define KCHUNK (NK / KSPLIT)   // 256

__device__ __align__(16) float g_qproj[NB * NQ * NH];   // [bq][h]
__device__ __align__(16) float g_kT[NB * NH * NK];      // [b][h][k]
__device__ __align__(16) float g_attn[NB * NQ * NK];    // [bq][k]
__device__ __align__(16) float g_part[NB * KSPLIT * NQ * ND];  // split-K partials

__device__ __forceinline__ __half2 h2tanh_fast(__half2 a) {
    __half2 r;
    asm("tanh.approx.f16x2 %0, %1;"
        : "=r"(*reinterpret_cast<unsigned int*>(&r))
        : "r"(*reinterpret_cast<unsigned int*>(&a)));
    return r;
}

__device__ __forceinline__ float cvt_tf32(float x) {
    unsigned u;
    asm("cvt.rna.tf32.f32 %0, %1;" : "=r"(u) : "f"(x));
    return __uint_as_float(u);
}

__device__ __forceinline__ void mma_tf32(float c[4], const unsigned a[4],
                                         const unsigned b[2]) {
    asm volatile(
        "mma.sync.aligned.m16n8k8.row.col.f32.tf32.tf32.f32 "
        "{%0,%1,%2,%3}, {%4,%5,%6,%7}, {%8,%9}, {%0,%1,%2,%3};"
        : "+f"(c[0]), "+f"(c[1]), "+f"(c[2]), "+f"(c[3])
        : "r"(a[0]), "r"(a[1]), "r"(a[2]), "r"(a[3]), "r"(b[0]), "r"(b[1]));
}

// ---------------------------------------------------------------------------
// smem helpers (k-major [BK][64+4])
// ---------------------------------------------------------------------------
__device__ __forceinline__ void stsT(float S[BK][BM + 4], float4 v, int lk, int row) {
    S[lk + 0][row] = v.x;
    S[lk + 1][row] = v.y;
    S[lk + 2][row] = v.z;
    S[lk + 3][row] = v.w;
}

__device__ __forceinline__ void stsT_tf32(float S[BK][BM + 4], float4 v, int lk, int row) {
    S[lk + 0][row] = cvt_tf32(v.x);
    S[lk + 1][row] = cvt_tf32(v.y);
    S[lk + 2][row] = cvt_tf32(v.z);
    S[lk + 3][row] = cvt_tf32(v.w);
}

// fp32 8x4 micro-tile (for av gemm)
__device__ __forceinline__ void mm_tile(const float As[BK][BM + 4],
                                        const float Bs[BK][BN + 4],
                                        float acc[TM][TN], int tx, int ty) {
#pragma unroll
    for (int kk = 0; kk < BK; kk++) {
        float4 a0 = *reinterpret_cast<const float4*>(&As[kk][ty * TM]);
        float4 a1 = *reinterpret_cast<const float4*>(&As[kk][ty * TM + 4]);
        float4 bv = *reinterpret_cast<const float4*>(&Bs[kk][tx * TN]);
        float a[8] = {a0.x, a0.y, a0.z, a0.w, a1.x, a1.y, a1.z, a1.w};
        float b[4] = {bv.x, bv.y, bv.z, bv.w};
#pragma unroll
        for (int i = 0; i < TM; i++)
#pragma unroll
            for (int j = 0; j < TN; j++)
                acc[i][j] = fmaf(a[i], b[j], acc[i][j]);
    }
}

// tf32 mma over one BK=16 slab; warp tile 32x32 (2 m16 x 4 n8 x 2 k8)
__device__ __forceinline__ void mma_slab(const float As[BK][BM + 4],
                                         const float Bs[BK][BN + 4],
                                         float acc[2][4][4], int wr, int wc, int lane) {
    const int qk = lane & 3, qr = lane >> 2;
#pragma unroll
    for (int ks = 0; ks < BK; ks += 8) {
        unsigned a[2][4], b[4][2];
#pragma unroll
        for (int mt = 0; mt < 2; mt++) {
            const int r = wr + mt * 16 + qr;
            a[mt][0] = __float_as_uint(As[ks + qk][r]);
            a[mt][1] = __float_as_uint(As[ks + qk][r + 8]);
            a[mt][2] = __float_as_uint(As[ks + 4 + qk][r]);
            a[mt][3] = __float_as_uint(As[ks + 4 + qk][r + 8]);
        }
#pragma unroll
        for (int nt = 0; nt < 4; nt++) {
            const int n = wc + nt * 8 + qr;
            b[nt][0] = __float_as_uint(Bs[ks + qk][n]);
            b[nt][1] = __float_as_uint(Bs[ks + 4 + qk][n]);
        }
#pragma unroll
        for (int mt = 0; mt < 2; mt++)
#pragma unroll
            for (int nt = 0; nt < 4; nt++)
                mma_tf32(acc[mt][nt], a[mt], b[nt]);
    }
}

// ---------------------------------------------------------------------------
// Fused q/k projection (NT GEMMs) via tf32 tensor cores.
//  bid <  64 : qproj  C[bq][h]    = queries(1024x512) @ Wq(256x512)^T
//  bid >= 64 : kproj  kT[b][h][k] = Wk(256x512) @ keys(4096x512)^T
// ---------------------------------------------------------------------------
__global__ void __launch_bounds__(128) proj_gemm(const float* __restrict__ Qin,
                                                 const float* __restrict__ Kin,
                                                 const float* __restrict__ Wq,
                                                 const float* __restrict__ Wk) {
    __shared__ __align__(16) float As[BK][BM + 4];
    __shared__ __align__(16) float Bs[BK][BN + 4];
    const int K = 512;
    const int bid = blockIdx.x, tid = threadIdx.x;

    const float *A, *B;
    int m0, n0;
    const bool isq = bid < 64;
    if (isq) {
        m0 = (bid >> 2) * BM;
        n0 = (bid & 3) * BN;
        A = Qin; B = Wq;
    } else {
        const int kb = bid - 64;
        m0 = (kb >> 6) * BM;   // h tiles (256)
        n0 = (kb & 63) * BN;   // (b,k) tiles (4096)
        A = Wk; B = Kin;
    }

    const int lr = tid >> 2;
    const int lk = (tid & 3) << 2;
    const float* Ap = A + (size_t)(m0 + lr) * K + lk;
    const float* Bp = B + (size_t)(n0 + lr) * K + lk;

    float4 a0 = *(const float4*)Ap;
    float4 a1 = *(const float4*)(Ap + 32 * K);
    float4 b0 = *(const float4*)Bp;
    float4 b1 = *(const float4*)(Bp + 32 * K);
    stsT_tf32(As, a0, lk, lr); stsT_tf32(As, a1, lk, lr + 32);
    stsT_tf32(Bs, b0, lk, lr); stsT_tf32(Bs, b1, lk, lr + 32);
    __syncthreads();

    float acc[2][4][4] = {};
    const int lane = tid & 31, wid = tid >> 5;
    const int wr = (wid & 1) * 32, wc = (wid >> 1) * 32;

    for (int k0 = BK; k0 < K; k0 += BK) {
        a0 = *(const float4*)(Ap + k0);
        a1 = *(const float4*)(Ap + 32 * K + k0);
        b0 = *(const float4*)(Bp + k0);
        b1 = *(const float4*)(Bp + 32 * K + k0);
        mma_slab(As, Bs, acc, wr, wc, lane);
        __syncthreads();
        stsT_tf32(As, a0, lk, lr); stsT_tf32(As, a1, lk, lr + 32);
        stsT_tf32(Bs, b0, lk, lr); stsT_tf32(Bs, b1, lk, lr + 32);
        __syncthreads();
    }
    mma_slab(As, Bs, acc, wr, wc, lane);

#pragma unroll
    for (int mt = 0; mt < 2; mt++) {
#pragma unroll
        for (int nt = 0; nt < 4; nt++) {
            const int r0 = m0 + wr + mt * 16 + (lane >> 2);
            const int cn = wc + nt * 8 + 2 * (lane & 3);
            float2 lo = make_float2(acc[mt][nt][0], acc[mt][nt][1]);
            float2 hi = make_float2(acc[mt][nt][2], acc[mt][nt][3]);
            if (isq) {
                *(float2*)&g_qproj[(size_t)r0 * NH + n0 + cn] = lo;
                *(float2*)&g_qproj[(size_t)(r0 + 8) * NH + n0 + cn] = hi;
            } else {
                const int gb = n0 >> 10;
                const int kx = (n0 & 1023) + cn;
                *(float2*)&g_kT[(size_t)(gb * NH + r0) * NK + kx] = lo;
                *(float2*)&g_kT[(size_t)(gb * NH + r0 + 8) * NK + kx] = hi;
            }
        }
    }
}

// ---------------------------------------------------------------------------
// Scores + masked softmax. 128 blocks, 512 threads.
// ---------------------------------------------------------------------------
__global__ void __launch_bounds__(512) scores_kernel(const int* __restrict__ vlen,
                                                     const float* __restrict__ wv) {
    __shared__ float qsT[NH][8];
    __shared__ __half2 qsh[NH][4];
    __shared__ float wvs[NH];
    __shared__ float wred[16][8];
    __shared__ float bred[8];

    const int tid = threadIdx.x;
    const int b = blockIdx.x >> 5;
    const int q0 = (blockIdx.x & 31) << 3;

    if (tid < NH) wvs[tid] = wv[tid];
#pragma unroll
    for (int i = 0; i < 4; i++) {
        const int idx = tid + i * 512;
        const int h = idx >> 3, r = idx & 7;
        qsT[h][r] = g_qproj[(size_t)(b * NQ + q0 + r) * NH + h];
    }
    __syncthreads();
#pragma unroll
    for (int i = 0; i < 2; i++) {
        const int idx = tid + i * 512;
        const int h = idx >> 2, rp = idx & 3;
        qsh[h][rp] = __floats2half2_rn(qsT[h][2 * rp], qsT[h][2 * rp + 1]);
    }
    __syncthreads();

    float acc[8][2] = {};
    const float2* kp = reinterpret_cast<const float2*>(g_kT + (size_t)b * NH * NK) + tid;

#pragma unroll 4
    for (int h = 0; h < NH; h++) {
        const float2 kv = kp[h * (NK / 2)];
        const __half2 k0 = __float2half2_rn(kv.x);
        const __half2 k1 = __float2half2_rn(kv.y);
        const float w = wvs[h];
#pragma unroll
        for (int rp = 0; rp < 4; rp++) {
            const __half2 q2 = qsh[h][rp];
            const float2 f0 = __half22float2(h2tanh_fast(__hadd2(q2, k0)));
            const float2 f1 = __half22float2(h2tanh_fast(__hadd2(q2, k1)));
            acc[2 * rp][0]     = fmaf(w, f0.x, acc[2 * rp][0]);
            acc[2 * rp + 1][0] = fmaf(w, f0.y, acc[2 * rp + 1][0]);
            acc[2 * rp][1]     = fmaf(w, f1.x, acc[2 * rp][1]);
            acc[2 * rp + 1][1] = fmaf(w, f1.y, acc[2 * rp + 1][1]);
        }
    }

    const int vl = vlen[b];
    const int kb2 = tid * 2;
    float s0[8], s1[8], rm[8];
#pragma unroll
    for (int r = 0; r < 8; r++) {
        s0[r] = (kb2 < vl) ? acc[r][0] : -1e6f;
        s1[r] = (kb2 + 1 < vl) ? acc[r][1] : -1e6f;
        rm[r] = fmaxf(s0[r], s1[r]);
    }
#pragma unroll
    for (int o = 16; o > 0; o >>= 1)
#pragma unroll
        for (int r = 0; r < 8; r++)
            rm[r] = fmaxf(rm[r], __shfl_xor_sync(0xffffffffu, rm[r], o));
    const int wid = tid >> 5, lane = tid & 31;
    if (lane == 0)
#pragma unroll
        for (int r = 0; r < 8; r++) wred[wid][r] = rm[r];
    __syncthreads();
    if (tid < 8) {
        float m = wred[0][tid];
#pragma unroll
        for (int w2 = 1; w2 < 16; w2++) m = fmaxf(m, wred[w2][tid]);
        bred[tid] = m;
    }
    __syncthreads();

    float e0[8], e1[8], rs[8];
#pragma unroll
    for (int r = 0; r < 8; r++) {
        const float mx = bred[r];
        e0[r] = __expf(s0[r] - mx);
        e1[r] = __expf(s1[r] - mx);
        rs[r] = e0[r] + e1[r];
    }
#pragma unroll
    for (int o = 16; o > 0; o >>= 1)
#pragma unroll
        for (int r = 0; r < 8; r++)
            rs[r] += __shfl_xor_sync(0xffffffffu, rs[r], o);
    if (lane == 0)
#pragma unroll
        for (int r = 0; r < 8; r++) wred[wid][r] = rs[r];
    __syncthreads();
    if (tid < 8) {
        float s = 0.0f;
#pragma unroll
        for (int w2 = 0; w2 < 16; w2++) s += wred[w2][tid];
        bred[tid] = 1.0f / s;
    }
    __syncthreads();

#pragma unroll
    for (int r = 0; r < 8; r++) {
        const float inv = bred[r];
        float2 o2 = make_float2(e0[r] * inv, e1[r] * inv);
        *reinterpret_cast<float2*>(&g_attn[(size_t)(b * NQ + q0 + r) * NK + kb2]) = o2;
    }
}

// ---------------------------------------------------------------------------
// Split-K attn @ values: partials to g_part, fp32 FFMA.
// ---------------------------------------------------------------------------
__global__ void __launch_bounds__(128) av_gemm(const float* __restrict__ V) {
    __shared__ __align__(16) float As[BK][BM + 4];
    __shared__ __align__(16) float Bs[BK][BN + 4];
    const int tid = threadIdx.x;
    const int b = blockIdx.z >> 2;
    const int split = blockIdx.z & 3;
    const int kbase = split * KCHUNK;
    const int m0 = blockIdx.y * BM;
    const int n0 = blockIdx.x * BN;
    const float* A = g_attn + (size_t)b * NQ * NK;
    const float* B = V + (size_t)b * NK * ND;

    const int lr = tid >> 2, lk = (tid & 3) << 2;
    const int bk = tid >> 4, bn = (tid & 15) << 2;
    const float* Ap = A + (size_t)(m0 + lr) * NK + lk;
    const float* Bp = B + (size_t)bk * ND + n0 + bn;

    float4 a0 = *(const float4*)(Ap + kbase);
    float4 a1 = *(const float4*)(Ap + 32 * NK + kbase);
    float4 b0 = *(const float4*)(Bp + (size_t)kbase * ND);
    float4 b1 = *(const float4*)(Bp + (size_t)(kbase + 8) * ND);
    stsT(As, a0, lk, lr); stsT(As, a1, lk, lr + 32);
    *(float4*)&Bs[bk][bn] = b0;
    *(float4*)&Bs[bk + 8][bn] = b1;
    __syncthreads();

    float acc[TM][TN] = {};
    const int tx = tid & 15, ty = tid >> 4;

    for (int k0 = kbase + BK; k0 < kbase + KCHUNK; k0 += BK) {
        a0 = *(const float4*)(Ap + k0);
        a1 = *(const float4*)(Ap + 32 * NK + k0);
        b0 = *(const float4*)(Bp + (size_t)k0 * ND);
        b1 = *(const float4*)(Bp + (size_t)(k0 + 8) * ND);
        mm_tile(As, Bs, acc, tx, ty);
        __syncthreads();
        stsT(As, a0, lk, lr); stsT(As, a1, lk, lr + 32);
        *(float4*)&Bs[bk][bn] = b0;
        *(float4*)&Bs[bk + 8][bn] = b1;
        __syncthreads();
    }
    mm_tile(As, Bs, acc, tx, ty);

    float* P = g_part + (size_t)(b * KSPLIT + split) * NQ * ND;
#pragma unroll
    for (int i = 0; i < TM; i++) {
        const int gm = m0 + ty * TM + i;
        float4 v = make_float4(acc[i][0], acc[i][1], acc[i][2], acc[i][3]);
        *(float4*)&P[(size_t)gm * ND + n0 + tx * TN] = v;
    }
}

__global__ void __launch_bounds__(256) reduce_kernel(float* __restrict__ out) {
    const int i = blockIdx.x * 256 + threadIdx.x;   // float4 index, 131072 total
    const int b = i >> 15;
    const int off = i & 32767;
    const float4* p = (const float4*)g_part;
    float4 s = p[(size_t)(b * KSPLIT + 0) * 32768 + off];
    float4 s1 = p[(size_t)(b * KSPLIT + 1) * 32768 + off];
    float4 s2 = p[(size_t)(b * KSPLIT + 2) * 32768 + off];
    float4 s3 = p[(size_t)(b * KSPLIT + 3) * 32768 + off];
    s.x += s1.x + s2.x + s3.x;
    s.y += s1.y + s2.y + s3.y;
    s.z += s1.z + s2.z + s3.z;
    s.w += s1.w + s2.w + s3.w;
    ((float4*)out)[i] = s;
}

// ---------------------------------------------------------------------------
extern "C" void kernel_launch(void* const* d_in, const int* in_sizes, int n_in,
                              void* d_out, int out_size) {
    const float* queries    = (const float*)d_in[0];
    const float* keys       = (const float*)d_in[1];
    const float* values     = (const float*)d_in[2];
    const int*   valid_lens = (const int*)d_in[3];
    const float* Wq         = (const float*)d_in[4];
    const float* Wk         = (const float*)d_in[5];
    const float* wv         = (const float*)d_in[6];
    float* out = (float*)d_out;

    (void)in_sizes; (void)n_in; (void)out_size;

    proj_gemm<<<320, 128>>>(queries, keys, Wq, Wk);
    scores_kernel<<<128, 512>>>(valid_lens, wv);
    av_gemm<<<dim3(ND / BN, NQ / BM, NB * KSPLIT), 128>>>(values);
    reduce_kernel<<<512, 256>>>(out);
}

// round 5
// speedup vs baseline: 1.4045x; 1.0639x over previous
#include <cuda_runtime.h>
#include <cuda_fp16.h>

// Problem constants
#define NB 4
#define NQ 256
#define NK 1024
#define ND 512
#define NH 256

// GEMM tiling
#define BM 64
#define BN 64
#define BK 16
#define KSPLIT 4
#define KCHUNK (NK / KSPLIT)   // 256

__device__ __align__(16) float g_qproj[NB * NQ * NH];   // [bq][h]
__device__ __align__(16) float g_kT[NB * NH * NK];      // [b][h][k]
__device__ __align__(16) float g_attn[NB * NQ * NK];    // [bq][k]
__device__ __align__(16) float g_part[NB * KSPLIT * NQ * ND];  // split-K partials

__device__ __forceinline__ __half2 h2tanh_fast(__half2 a) {
    __half2 r;
    asm("tanh.approx.f16x2 %0, %1;"
        : "=r"(*reinterpret_cast<unsigned int*>(&r))
        : "r"(*reinterpret_cast<unsigned int*>(&a)));
    return r;
}

__device__ __forceinline__ float cvt_tf32(float x) {
    unsigned u;
    asm("cvt.rna.tf32.f32 %0, %1;" : "=r"(u) : "f"(x));
    return __uint_as_float(u);
}

__device__ __forceinline__ void mma_tf32(float c[4], const unsigned a[4],
                                         const unsigned b[2]) {
    asm volatile(
        "mma.sync.aligned.m16n8k8.row.col.f32.tf32.tf32.f32 "
        "{%0,%1,%2,%3}, {%4,%5,%6,%7}, {%8,%9}, {%0,%1,%2,%3};"
        : "+f"(c[0]), "+f"(c[1]), "+f"(c[2]), "+f"(c[3])
        : "r"(a[0]), "r"(a[1]), "r"(a[2]), "r"(a[3]), "r"(b[0]), "r"(b[1]));
}

// ---------------------------------------------------------------------------
// smem helpers (k-major [BK][64+4])
// ---------------------------------------------------------------------------
__device__ __forceinline__ void stsT_tf32(float S[BK][BM + 4], float4 v, int lk, int row) {
    S[lk + 0][row] = cvt_tf32(v.x);
    S[lk + 1][row] = cvt_tf32(v.y);
    S[lk + 2][row] = cvt_tf32(v.z);
    S[lk + 3][row] = cvt_tf32(v.w);
}

__device__ __forceinline__ float4 cvt4_tf32(float4 v) {
    return make_float4(cvt_tf32(v.x), cvt_tf32(v.y), cvt_tf32(v.z), cvt_tf32(v.w));
}

// tf32 mma over one BK=16 slab; warp tile 32x32 (2 m16 x 4 n8 x 2 k8)
__device__ __forceinline__ void mma_slab(const float As[BK][BM + 4],
                                         const float Bs[BK][BN + 4],
                                         float acc[2][4][4], int wr, int wc, int lane) {
    const int qk = lane & 3, qr = lane >> 2;
#pragma unroll
    for (int ks = 0; ks < BK; ks += 8) {
        unsigned a[2][4], b[4][2];
#pragma unroll
        for (int mt = 0; mt < 2; mt++) {
            const int r = wr + mt * 16 + qr;
            a[mt][0] = __float_as_uint(As[ks + qk][r]);
            a[mt][1] = __float_as_uint(As[ks + qk][r + 8]);
            a[mt][2] = __float_as_uint(As[ks + 4 + qk][r]);
            a[mt][3] = __float_as_uint(As[ks + 4 + qk][r + 8]);
        }
#pragma unroll
        for (int nt = 0; nt < 4; nt++) {
            const int n = wc + nt * 8 + qr;
            b[nt][0] = __float_as_uint(Bs[ks + qk][n]);
            b[nt][1] = __float_as_uint(Bs[ks + 4 + qk][n]);
        }
#pragma unroll
        for (int mt = 0; mt < 2; mt++)
#pragma unroll
            for (int nt = 0; nt < 4; nt++)
                mma_tf32(acc[mt][nt], a[mt], b[nt]);
    }
}

// ---------------------------------------------------------------------------
// Fused q/k projection (NT GEMMs) via tf32 tensor cores.
// ---------------------------------------------------------------------------
__global__ void __launch_bounds__(128) proj_gemm(const float* __restrict__ Qin,
                                                 const float* __restrict__ Kin,
                                                 const float* __restrict__ Wq,
                                                 const float* __restrict__ Wk) {
    __shared__ __align__(16) float As[BK][BM + 4];
    __shared__ __align__(16) float Bs[BK][BN + 4];
    const int K = 512;
    const int bid = blockIdx.x, tid = threadIdx.x;

    const float *A, *B;
    int m0, n0;
    const bool isq = bid < 64;
    if (isq) {
        m0 = (bid >> 2) * BM;
        n0 = (bid & 3) * BN;
        A = Qin; B = Wq;
    } else {
        const int kb = bid - 64;
        m0 = (kb >> 6) * BM;   // h tiles (256)
        n0 = (kb & 63) * BN;   // (b,k) tiles (4096)
        A = Wk; B = Kin;
    }

    const int lr = tid >> 2;
    const int lk = (tid & 3) << 2;
    const float* Ap = A + (size_t)(m0 + lr) * K + lk;
    const float* Bp = B + (size_t)(n0 + lr) * K + lk;

    float4 a0 = *(const float4*)Ap;
    float4 a1 = *(const float4*)(Ap + 32 * K);
    float4 b0 = *(const float4*)Bp;
    float4 b1 = *(const float4*)(Bp + 32 * K);
    stsT_tf32(As, a0, lk, lr); stsT_tf32(As, a1, lk, lr + 32);
    stsT_tf32(Bs, b0, lk, lr); stsT_tf32(Bs, b1, lk, lr + 32);
    __syncthreads();

    float acc[2][4][4] = {};
    const int lane = tid & 31, wid = tid >> 5;
    const int wr = (wid & 1) * 32, wc = (wid >> 1) * 32;

    for (int k0 = BK; k0 < K; k0 += BK) {
        a0 = *(const float4*)(Ap + k0);
        a1 = *(const float4*)(Ap + 32 * K + k0);
        b0 = *(const float4*)(Bp + k0);
        b1 = *(const float4*)(Bp + 32 * K + k0);
        mma_slab(As, Bs, acc, wr, wc, lane);
        __syncthreads();
        stsT_tf32(As, a0, lk, lr); stsT_tf32(As, a1, lk, lr + 32);
        stsT_tf32(Bs, b0, lk, lr); stsT_tf32(Bs, b1, lk, lr + 32);
        __syncthreads();
    }
    mma_slab(As, Bs, acc, wr, wc, lane);

#pragma unroll
    for (int mt = 0; mt < 2; mt++) {
#pragma unroll
        for (int nt = 0; nt < 4; nt++) {
            const int r0 = m0 + wr + mt * 16 + (lane >> 2);
            const int cn = wc + nt * 8 + 2 * (lane & 3);
            float2 lo = make_float2(acc[mt][nt][0], acc[mt][nt][1]);
            float2 hi = make_float2(acc[mt][nt][2], acc[mt][nt][3]);
            if (isq) {
                *(float2*)&g_qproj[(size_t)r0 * NH + n0 + cn] = lo;
                *(float2*)&g_qproj[(size_t)(r0 + 8) * NH + n0 + cn] = hi;
            } else {
                const int gb = n0 >> 10;
                const int kx = (n0 & 1023) + cn;
                *(float2*)&g_kT[(size_t)(gb * NH + r0) * NK + kx] = lo;
                *(float2*)&g_kT[(size_t)(gb * NH + r0 + 8) * NK + kx] = hi;
            }
        }
    }
}

// ---------------------------------------------------------------------------
// Scores + masked softmax. 128 blocks, 512 threads.
// ---------------------------------------------------------------------------
__global__ void __launch_bounds__(512) scores_kernel(const int* __restrict__ vlen,
                                                     const float* __restrict__ wv) {
    __shared__ float qsT[NH][8];
    __shared__ __half2 qsh[NH][4];
    __shared__ float wvs[NH];
    __shared__ float wred[16][8];
    __shared__ float bred[8];

    const int tid = threadIdx.x;
    const int b = blockIdx.x >> 5;
    const int q0 = (blockIdx.x & 31) << 3;

    if (tid < NH) wvs[tid] = wv[tid];
#pragma unroll
    for (int i = 0; i < 4; i++) {
        const int idx = tid + i * 512;
        const int h = idx >> 3, r = idx & 7;
        qsT[h][r] = g_qproj[(size_t)(b * NQ + q0 + r) * NH + h];
    }
    __syncthreads();
#pragma unroll
    for (int i = 0; i < 2; i++) {
        const int idx = tid + i * 512;
        const int h = idx >> 2, rp = idx & 3;
        qsh[h][rp] = __floats2half2_rn(qsT[h][2 * rp], qsT[h][2 * rp + 1]);
    }
    __syncthreads();

    float acc[8][2] = {};
    const float2* kp = reinterpret_cast<const float2*>(g_kT + (size_t)b * NH * NK) + tid;

#pragma unroll 4
    for (int h = 0; h < NH; h++) {
        const float2 kv = kp[h * (NK / 2)];
        const __half2 k0 = __float2half2_rn(kv.x);
        const __half2 k1 = __float2half2_rn(kv.y);
        const float w = wvs[h];
#pragma unroll
        for (int rp = 0; rp < 4; rp++) {
            const __half2 q2 = qsh[h][rp];
            const float2 f0 = __half22float2(h2tanh_fast(__hadd2(q2, k0)));
            const float2 f1 = __half22float2(h2tanh_fast(__hadd2(q2, k1)));
            acc[2 * rp][0]     = fmaf(w, f0.x, acc[2 * rp][0]);
            acc[2 * rp + 1][0] = fmaf(w, f0.y, acc[2 * rp + 1][0]);
            acc[2 * rp][1]     = fmaf(w, f1.x, acc[2 * rp][1]);
            acc[2 * rp + 1][1] = fmaf(w, f1.y, acc[2 * rp + 1][1]);
        }
    }

    const int vl = vlen[b];
    const int kb2 = tid * 2;
    float s0[8], s1[8], rm[8];
#pragma unroll
    for (int r = 0; r < 8; r++) {
        s0[r] = (kb2 < vl) ? acc[r][0] : -1e6f;
        s1[r] = (kb2 + 1 < vl) ? acc[r][1] : -1e6f;
        rm[r] = fmaxf(s0[r], s1[r]);
    }
#pragma unroll
    for (int o = 16; o > 0; o >>= 1)
#pragma unroll
        for (int r = 0; r < 8; r++)
            rm[r] = fmaxf(rm[r], __shfl_xor_sync(0xffffffffu, rm[r], o));
    const int wid = tid >> 5, lane = tid & 31;
    if (lane == 0)
#pragma unroll
        for (int r = 0; r < 8; r++) wred[wid][r] = rm[r];
    __syncthreads();
    if (tid < 8) {
        float m = wred[0][tid];
#pragma unroll
        for (int w2 = 1; w2 < 16; w2++) m = fmaxf(m, wred[w2][tid]);
        bred[tid] = m;
    }
    __syncthreads();

    float e0[8], e1[8], rs[8];
#pragma unroll
    for (int r = 0; r < 8; r++) {
        const float mx = bred[r];
        e0[r] = __expf(s0[r] - mx);
        e1[r] = __expf(s1[r] - mx);
        rs[r] = e0[r] + e1[r];
    }
#pragma unroll
    for (int o = 16; o > 0; o >>= 1)
#pragma unroll
        for (int r = 0; r < 8; r++)
            rs[r] += __shfl_xor_sync(0xffffffffu, rs[r], o);
    if (lane == 0)
#pragma unroll
        for (int r = 0; r < 8; r++) wred[wid][r] = rs[r];
    __syncthreads();
    if (tid < 8) {
        float s = 0.0f;
#pragma unroll
        for (int w2 = 0; w2 < 16; w2++) s += wred[w2][tid];
        bred[tid] = 1.0f / s;
    }
    __syncthreads();

#pragma unroll
    for (int r = 0; r < 8; r++) {
        const float inv = bred[r];
        float2 o2 = make_float2(e0[r] * inv, e1[r] * inv);
        *reinterpret_cast<float2*>(&g_attn[(size_t)(b * NQ + q0 + r) * NK + kb2]) = o2;
    }
}

// ---------------------------------------------------------------------------
// Split-K attn @ values via tf32 tensor cores; partials to g_part.
// ---------------------------------------------------------------------------
__global__ void __launch_bounds__(128) av_gemm(const float* __restrict__ V) {
    __shared__ __align__(16) float As[BK][BM + 4];
    __shared__ __align__(16) float Bs[BK][BN + 4];
    const int tid = threadIdx.x;
    const int b = blockIdx.z >> 2;
    const int split = blockIdx.z & 3;
    const int kbase = split * KCHUNK;
    const int m0 = blockIdx.y * BM;
    const int n0 = blockIdx.x * BN;
    const float* A = g_attn + (size_t)b * NQ * NK;
    const float* B = V + (size_t)b * NK * ND;

    const int lr = tid >> 2, lk = (tid & 3) << 2;   // A (transpose) loader
    const int bk = tid >> 4, bn = (tid & 15) << 2;  // B (direct) loader
    const float* Ap = A + (size_t)(m0 + lr) * NK + lk;
    const float* Bp = B + (size_t)bk * ND + n0 + bn;

    float4 a0 = *(const float4*)(Ap + kbase);
    float4 a1 = *(const float4*)(Ap + 32 * NK + kbase);
    float4 b0 = *(const float4*)(Bp + (size_t)kbase * ND);
    float4 b1 = *(const float4*)(Bp + (size_t)(kbase + 8) * ND);
    stsT_tf32(As, a0, lk, lr); stsT_tf32(As, a1, lk, lr + 32);
    *(float4*)&Bs[bk][bn] = cvt4_tf32(b0);
    *(float4*)&Bs[bk + 8][bn] = cvt4_tf32(b1);
    __syncthreads();

    float acc[2][4][4] = {};
    const int lane = tid & 31, wid = tid >> 5;
    const int wr = (wid & 1) * 32, wc = (wid >> 1) * 32;

    for (int k0 = kbase + BK; k0 < kbase + KCHUNK; k0 += BK) {
        a0 = *(const float4*)(Ap + k0);
        a1 = *(const float4*)(Ap + 32 * NK + k0);
        b0 = *(const float4*)(Bp + (size_t)k0 * ND);
        b1 = *(const float4*)(Bp + (size_t)(k0 + 8) * ND);
        mma_slab(As, Bs, acc, wr, wc, lane);
        __syncthreads();
        stsT_tf32(As, a0, lk, lr); stsT_tf32(As, a1, lk, lr + 32);
        *(float4*)&Bs[bk][bn] = cvt4_tf32(b0);
        *(float4*)&Bs[bk + 8][bn] = cvt4_tf32(b1);
        __syncthreads();
    }
    mma_slab(As, Bs, acc, wr, wc, lane);

    float* P = g_part + (size_t)(b * KSPLIT + split) * NQ * ND;
#pragma unroll
    for (int mt = 0; mt < 2; mt++) {
#pragma unroll
        for (int nt = 0; nt < 4; nt++) {
            const int r0 = m0 + wr + mt * 16 + (lane >> 2);
            const int cn = n0 + wc + nt * 8 + 2 * (lane & 3);
            float2 lo = make_float2(acc[mt][nt][0], acc[mt][nt][1]);
            float2 hi = make_float2(acc[mt][nt][2], acc[mt][nt][3]);
            *(float2*)&P[(size_t)r0 * ND + cn] = lo;
            *(float2*)&P[(size_t)(r0 + 8) * ND + cn] = hi;
        }
    }
}

__global__ void __launch_bounds__(256) reduce_kernel(float* __restrict__ out) {
    const int i = blockIdx.x * 256 + threadIdx.x;   // float4 index, 131072 total
    const int b = i >> 15;
    const int off = i & 32767;
    const float4* p = (const float4*)g_part;
    float4 s = p[(size_t)(b * KSPLIT + 0) * 32768 + off];
    float4 s1 = p[(size_t)(b * KSPLIT + 1) * 32768 + off];
    float4 s2 = p[(size_t)(b * KSPLIT + 2) * 32768 + off];
    float4 s3 = p[(size_t)(b * KSPLIT + 3) * 32768 + off];
    s.x += s1.x + s2.x + s3.x;
    s.y += s1.y + s2.y + s3.y;
    s.z += s1.z + s2.z + s3.z;
    s.w += s1.w + s2.w + s3.w;
    ((float4*)out)[i] = s;
}

// ---------------------------------------------------------------------------
extern "C" void kernel_launch(void* const* d_in, const int* in_sizes, int n_in,
                              void* d_out, int out_size) {
    const float* queries    = (const float*)d_in[0];
    const float* keys       = (const float*)d_in[1];
    const float* values     = (const float*)d_in[2];
    const int*   valid_lens = (const int*)d_in[3];
    const float* Wq         = (const float*)d_in[4];
    const float* Wk         = (const float*)d_in[5];
    const float* wv         = (const float*)d_in[6];
    float* out = (float*)d_out;

    (void)in_sizes; (void)n_in; (void)out_size;

    proj_gemm<<<320, 128>>>(queries, keys, Wq, Wk);
    scores_kernel<<<128, 512>>>(valid_lens, wv);
    av_gemm<<<dim3(ND / BN, NQ / BM, NB * KSPLIT), 128>>>(values);
    reduce_kernel<<<512, 256>>>(out);
}

// round 6
// speedup vs baseline: 1.8457x; 1.3142x over previous
#include <cuda_runtime.h>
#include <cuda_fp16.h>

// Problem constants
#define NB 4
#define NQ 256
#define NK 1024
#define ND 512
#define NH 256

// GEMM tiling
#define BM 64
#define BN 64
#define BK 16
#define KSPLIT 4
#define KCHUNK (NK / KSPLIT)   // 256

__device__ __align__(16) float g_qproj[NB * NQ * NH];   // [bq][h]
__device__ __align__(16) float g_kT[NB * NH * NK];      // [b][h][k]
__device__ __align__(16) float g_attn[NB * NQ * NK];    // [bq][k]
__device__ __align__(16) float g_part[NB * KSPLIT * NQ * ND];  // split-K partials

__device__ __forceinline__ __half2 h2tanh_fast(__half2 a) {
    __half2 r;
    asm("tanh.approx.f16x2 %0, %1;"
        : "=r"(*reinterpret_cast<unsigned int*>(&r))
        : "r"(*reinterpret_cast<unsigned int*>(&a)));
    return r;
}

__device__ __forceinline__ float cvt_tf32(float x) {
    unsigned u;
    asm("cvt.rna.tf32.f32 %0, %1;" : "=r"(u) : "f"(x));
    return __uint_as_float(u);
}

__device__ __forceinline__ void mma_tf32(float c[4], const unsigned a[4],
                                         const unsigned b[2]) {
    asm volatile(
        "mma.sync.aligned.m16n8k8.row.col.f32.tf32.tf32.f32 "
        "{%0,%1,%2,%3}, {%4,%5,%6,%7}, {%8,%9}, {%0,%1,%2,%3};"
        : "+f"(c[0]), "+f"(c[1]), "+f"(c[2]), "+f"(c[3])
        : "r"(a[0]), "r"(a[1]), "r"(a[2]), "r"(a[3]), "r"(b[0]), "r"(b[1]));
}

// ---------------------------------------------------------------------------
// smem helpers (k-major [BK][64+4])
// ---------------------------------------------------------------------------
__device__ __forceinline__ void stsT_tf32(float S[BK][BM + 4], float4 v, int lk, int row) {
    S[lk + 0][row] = cvt_tf32(v.x);
    S[lk + 1][row] = cvt_tf32(v.y);
    S[lk + 2][row] = cvt_tf32(v.z);
    S[lk + 3][row] = cvt_tf32(v.w);
}

__device__ __forceinline__ float4 cvt4_tf32(float4 v) {
    return make_float4(cvt_tf32(v.x), cvt_tf32(v.y), cvt_tf32(v.z), cvt_tf32(v.w));
}

// tf32 mma over one BK=16 slab; warp tile 32x32 (2 m16 x 4 n8 x 2 k8)
__device__ __forceinline__ void mma_slab(const float As[BK][BM + 4],
                                         const float Bs[BK][BN + 4],
                                         float acc[2][4][4], int wr, int wc, int lane) {
    const int qk = lane & 3, qr = lane >> 2;
#pragma unroll
    for (int ks = 0; ks < BK; ks += 8) {
        unsigned a[2][4], b[4][2];
#pragma unroll
        for (int mt = 0; mt < 2; mt++) {
            const int r = wr + mt * 16 + qr;
            a[mt][0] = __float_as_uint(As[ks + qk][r]);
            a[mt][1] = __float_as_uint(As[ks + qk][r + 8]);
            a[mt][2] = __float_as_uint(As[ks + 4 + qk][r]);
            a[mt][3] = __float_as_uint(As[ks + 4 + qk][r + 8]);
        }
#pragma unroll
        for (int nt = 0; nt < 4; nt++) {
            const int n = wc + nt * 8 + qr;
            b[nt][0] = __float_as_uint(Bs[ks + qk][n]);
            b[nt][1] = __float_as_uint(Bs[ks + 4 + qk][n]);
        }
#pragma unroll
        for (int mt = 0; mt < 2; mt++)
#pragma unroll
            for (int nt = 0; nt < 4; nt++)
                mma_tf32(acc[mt][nt], a[mt], b[nt]);
    }
}

// ---------------------------------------------------------------------------
// Fused q/k projection (NT GEMMs) via tf32 tensor cores.
// kproj tiles fully beyond valid_len are skipped (their outputs are never read).
// ---------------------------------------------------------------------------
__global__ void __launch_bounds__(128) proj_gemm(const float* __restrict__ Qin,
                                                 const float* __restrict__ Kin,
                                                 const float* __restrict__ Wq,
                                                 const float* __restrict__ Wk,
                                                 const int* __restrict__ vlen) {
    __shared__ __align__(16) float As[BK][BM + 4];
    __shared__ __align__(16) float Bs[BK][BN + 4];
    const int K = 512;
    const int bid = blockIdx.x, tid = threadIdx.x;

    const float *A, *B;
    int m0, n0;
    const bool isq = bid < 64;
    if (isq) {
        m0 = (bid >> 2) * BM;
        n0 = (bid & 3) * BN;
        A = Qin; B = Wq;
    } else {
        const int kb = bid - 64;
        m0 = (kb >> 6) * BM;   // h tiles (256)
        n0 = (kb & 63) * BN;   // (b,k) tiles (4096)
        // dead k-tile: no consumer ever reads g_kT for k >= vlen[b]
        if ((n0 & 1023) >= vlen[n0 >> 10]) return;
        A = Wk; B = Kin;
    }

    const int lr = tid >> 2;
    const int lk = (tid & 3) << 2;
    const float* Ap = A + (size_t)(m0 + lr) * K + lk;
    const float* Bp = B + (size_t)(n0 + lr) * K + lk;

    float4 a0 = *(const float4*)Ap;
    float4 a1 = *(const float4*)(Ap + 32 * K);
    float4 b0 = *(const float4*)Bp;
    float4 b1 = *(const float4*)(Bp + 32 * K);
    stsT_tf32(As, a0, lk, lr); stsT_tf32(As, a1, lk, lr + 32);
    stsT_tf32(Bs, b0, lk, lr); stsT_tf32(Bs, b1, lk, lr + 32);
    __syncthreads();

    float acc[2][4][4] = {};
    const int lane = tid & 31, wid = tid >> 5;
    const int wr = (wid & 1) * 32, wc = (wid >> 1) * 32;

    for (int k0 = BK; k0 < K; k0 += BK) {
        a0 = *(const float4*)(Ap + k0);
        a1 = *(const float4*)(Ap + 32 * K + k0);
        b0 = *(const float4*)(Bp + k0);
        b1 = *(const float4*)(Bp + 32 * K + k0);
        mma_slab(As, Bs, acc, wr, wc, lane);
        __syncthreads();
        stsT_tf32(As, a0, lk, lr); stsT_tf32(As, a1, lk, lr + 32);
        stsT_tf32(Bs, b0, lk, lr); stsT_tf32(Bs, b1, lk, lr + 32);
        __syncthreads();
    }
    mma_slab(As, Bs, acc, wr, wc, lane);

#pragma unroll
    for (int mt = 0; mt < 2; mt++) {
#pragma unroll
        for (int nt = 0; nt < 4; nt++) {
            const int r0 = m0 + wr + mt * 16 + (lane >> 2);
            const int cn = wc + nt * 8 + 2 * (lane & 3);
            float2 lo = make_float2(acc[mt][nt][0], acc[mt][nt][1]);
            float2 hi = make_float2(acc[mt][nt][2], acc[mt][nt][3]);
            if (isq) {
                *(float2*)&g_qproj[(size_t)r0 * NH + n0 + cn] = lo;
                *(float2*)&g_qproj[(size_t)(r0 + 8) * NH + n0 + cn] = hi;
            } else {
                const int gb = n0 >> 10;
                const int kx = (n0 & 1023) + cn;
                *(float2*)&g_kT[(size_t)(gb * NH + r0) * NK + kx] = lo;
                *(float2*)&g_kT[(size_t)(gb * NH + r0 + 8) * NK + kx] = hi;
            }
        }
    }
}

// ---------------------------------------------------------------------------
// Scores + masked softmax. 128 blocks, 512 threads.
// Threads whose keys are fully masked skip the tanh loop entirely (exact:
// their attention weights underflow to 0.0f regardless).
// ---------------------------------------------------------------------------
__global__ void __launch_bounds__(512) scores_kernel(const int* __restrict__ vlen,
                                                     const float* __restrict__ wv) {
    __shared__ float qsT[NH][8];
    __shared__ __half2 qsh[NH][4];
    __shared__ float wvs[NH];
    __shared__ float wred[16][8];
    __shared__ float bred[8];

    const int tid = threadIdx.x;
    const int b = blockIdx.x >> 5;
    const int q0 = (blockIdx.x & 31) << 3;
    const int vl = vlen[b];
    const int kb2 = tid * 2;

    if (tid < NH) wvs[tid] = wv[tid];
#pragma unroll
    for (int i = 0; i < 4; i++) {
        const int idx = tid + i * 512;
        const int h = idx >> 3, r = idx & 7;
        qsT[h][r] = g_qproj[(size_t)(b * NQ + q0 + r) * NH + h];
    }
    __syncthreads();
#pragma unroll
    for (int i = 0; i < 2; i++) {
        const int idx = tid + i * 512;
        const int h = idx >> 2, rp = idx & 3;
        qsh[h][rp] = __floats2half2_rn(qsT[h][2 * rp], qsT[h][2 * rp + 1]);
    }
    __syncthreads();

    float acc[8][2] = {};
    if (kb2 < vl) {   // fully-masked threads skip all loads + tanh work (exact)
        const float2* kp = reinterpret_cast<const float2*>(g_kT + (size_t)b * NH * NK) + tid;
#pragma unroll 4
        for (int h = 0; h < NH; h++) {
            const float2 kv = kp[h * (NK / 2)];
            const __half2 k0 = __float2half2_rn(kv.x);
            const __half2 k1 = __float2half2_rn(kv.y);
            const float w = wvs[h];
#pragma unroll
            for (int rp = 0; rp < 4; rp++) {
                const __half2 q2 = qsh[h][rp];
                const float2 f0 = __half22float2(h2tanh_fast(__hadd2(q2, k0)));
                const float2 f1 = __half22float2(h2tanh_fast(__hadd2(q2, k1)));
                acc[2 * rp][0]     = fmaf(w, f0.x, acc[2 * rp][0]);
                acc[2 * rp + 1][0] = fmaf(w, f0.y, acc[2 * rp + 1][0]);
                acc[2 * rp][1]     = fmaf(w, f1.x, acc[2 * rp][1]);
                acc[2 * rp + 1][1] = fmaf(w, f1.y, acc[2 * rp + 1][1]);
            }
        }
    }

    float s0[8], s1[8], rm[8];
#pragma unroll
    for (int r = 0; r < 8; r++) {
        s0[r] = (kb2 < vl) ? acc[r][0] : -1e6f;
        s1[r] = (kb2 + 1 < vl) ? acc[r][1] : -1e6f;
        rm[r] = fmaxf(s0[r], s1[r]);
    }
#pragma unroll
    for (int o = 16; o > 0; o >>= 1)
#pragma unroll
        for (int r = 0; r < 8; r++)
            rm[r] = fmaxf(rm[r], __shfl_xor_sync(0xffffffffu, rm[r], o));
    const int wid = tid >> 5, lane = tid & 31;
    if (lane == 0)
#pragma unroll
        for (int r = 0; r < 8; r++) wred[wid][r] = rm[r];
    __syncthreads();
    if (tid < 8) {
        float m = wred[0][tid];
#pragma unroll
        for (int w2 = 1; w2 < 16; w2++) m = fmaxf(m, wred[w2][tid]);
        bred[tid] = m;
    }
    __syncthreads();

    float e0[8], e1[8], rs[8];
#pragma unroll
    for (int r = 0; r < 8; r++) {
        const float mx = bred[r];
        e0[r] = __expf(s0[r] - mx);
        e1[r] = __expf(s1[r] - mx);
        rs[r] = e0[r] + e1[r];
    }
#pragma unroll
    for (int o = 16; o > 0; o >>= 1)
#pragma unroll
        for (int r = 0; r < 8; r++)
            rs[r] += __shfl_xor_sync(0xffffffffu, rs[r], o);
    if (lane == 0)
#pragma unroll
        for (int r = 0; r < 8; r++) wred[wid][r] = rs[r];
    __syncthreads();
    if (tid < 8) {
        float s = 0.0f;
#pragma unroll
        for (int w2 = 0; w2 < 16; w2++) s += wred[w2][tid];
        bred[tid] = 1.0f / s;
    }
    __syncthreads();

#pragma unroll
    for (int r = 0; r < 8; r++) {
        const float inv = bred[r];
        float2 o2 = make_float2(e0[r] * inv, e1[r] * inv);
        *reinterpret_cast<float2*>(&g_attn[(size_t)(b * NQ + q0 + r) * NK + kb2]) = o2;
    }
}

// ---------------------------------------------------------------------------
// Split-K attn @ values via tf32 tensor cores; partials to g_part.
// Chunks fully beyond valid_len skip the mainloop (attn there is exactly 0).
// ---------------------------------------------------------------------------
__global__ void __launch_bounds__(128) av_gemm(const float* __restrict__ V,
                                               const int* __restrict__ vlen) {
    __shared__ __align__(16) float As[BK][BM + 4];
    __shared__ __align__(16) float Bs[BK][BN + 4];
    const int tid = threadIdx.x;
    const int b = blockIdx.z >> 2;
    const int split = blockIdx.z & 3;
    const int kbase = split * KCHUNK;
    const int m0 = blockIdx.y * BM;
    const int n0 = blockIdx.x * BN;
    const int vl = vlen[b];

    float acc[2][4][4] = {};
    const int lane = tid & 31, wid = tid >> 5;
    const int wr = (wid & 1) * 32, wc = (wid >> 1) * 32;

    if (kbase < vl) {   // otherwise: entire chunk has attn == 0.0f exactly
        const float* A = g_attn + (size_t)b * NQ * NK;
        const float* B = V + (size_t)b * NK * ND;

        const int lr = tid >> 2, lk = (tid & 3) << 2;   // A (transpose) loader
        const int bk = tid >> 4, bn = (tid & 15) << 2;  // B (direct) loader
        const float* Ap = A + (size_t)(m0 + lr) * NK + lk;
        const float* Bp = B + (size_t)bk * ND + n0 + bn;

        float4 a0 = *(const float4*)(Ap + kbase);
        float4 a1 = *(const float4*)(Ap + 32 * NK + kbase);
        float4 b0 = *(const float4*)(Bp + (size_t)kbase * ND);
        float4 b1 = *(const float4*)(Bp + (size_t)(kbase + 8) * ND);
        stsT_tf32(As, a0, lk, lr); stsT_tf32(As, a1, lk, lr + 32);
        *(float4*)&Bs[bk][bn] = cvt4_tf32(b0);
        *(float4*)&Bs[bk + 8][bn] = cvt4_tf32(b1);
        __syncthreads();

        for (int k0 = kbase + BK; k0 < kbase + KCHUNK; k0 += BK) {
            a0 = *(const float4*)(Ap + k0);
            a1 = *(const float4*)(Ap + 32 * NK + k0);
            b0 = *(const float4*)(Bp + (size_t)k0 * ND);
            b1 = *(const float4*)(Bp + (size_t)(k0 + 8) * ND);
            mma_slab(As, Bs, acc, wr, wc, lane);
            __syncthreads();
            stsT_tf32(As, a0, lk, lr); stsT_tf32(As, a1, lk, lr + 32);
            *(float4*)&Bs[bk][bn] = cvt4_tf32(b0);
            *(float4*)&Bs[bk + 8][bn] = cvt4_tf32(b1);
            __syncthreads();
        }
        mma_slab(As, Bs, acc, wr, wc, lane);
    }

    float* P = g_part + (size_t)(b * KSPLIT + split) * NQ * ND;
#pragma unroll
    for (int mt = 0; mt < 2; mt++) {
#pragma unroll
        for (int nt = 0; nt < 4; nt++) {
            const int r0 = m0 + wr + mt * 16 + (lane >> 2);
            const int cn = n0 + wc + nt * 8 + 2 * (lane & 3);
            float2 lo = make_float2(acc[mt][nt][0], acc[mt][nt][1]);
            float2 hi = make_float2(acc[mt][nt][2], acc[mt][nt][3]);
            *(float2*)&P[(size_t)r0 * ND + cn] = lo;
            *(float2*)&P[(size_t)(r0 + 8) * ND + cn] = hi;
        }
    }
}

__global__ void __launch_bounds__(256) reduce_kernel(float* __restrict__ out) {
    const int i = blockIdx.x * 256 + threadIdx.x;   // float4 index, 131072 total
    const int b = i >> 15;
    const int off = i & 32767;
    const float4* p = (const float4*)g_part;
    float4 s = p[(size_t)(b * KSPLIT + 0) * 32768 + off];
    float4 s1 = p[(size_t)(b * KSPLIT + 1) * 32768 + off];
    float4 s2 = p[(size_t)(b * KSPLIT + 2) * 32768 + off];
    float4 s3 = p[(size_t)(b * KSPLIT + 3) * 32768 + off];
    s.x += s1.x + s2.x + s3.x;
    s.y += s1.y + s2.y + s3.y;
    s.z += s1.z + s2.z + s3.z;
    s.w += s1.w + s2.w + s3.w;
    ((float4*)out)[i] = s;
}

// ---------------------------------------------------------------------------
extern "C" void kernel_launch(void* const* d_in, const int* in_sizes, int n_in,
                              void* d_out, int out_size) {
    const float* queries    = (const float*)d_in[0];
    const float* keys       = (const float*)d_in[1];
    const float* values     = (const float*)d_in[2];
    const int*   valid_lens = (const int*)d_in[3];
    const float* Wq         = (const float*)d_in[4];
    const float* Wk         = (const float*)d_in[5];
    const float* wv         = (const float*)d_in[6];
    float* out = (float*)d_out;

    (void)in_sizes; (void)n_in; (void)out_size;

    proj_gemm<<<320, 128>>>(queries, keys, Wq, Wk, valid_lens);
    scores_kernel<<<128, 512>>>(valid_lens, wv);
    av_gemm<<<dim3(ND / BN, NQ / BM, NB * KSPLIT), 128>>>(values, valid_lens);
    reduce_kernel<<<512, 256>>>(out);
}